// round 1
// baseline (speedup 1.0000x reference)
#include <cuda_runtime.h>

// Problem constants
#define BB   4
#define HH   256
#define WW   256
#define CC   32        // channels (8 float4 groups)
#define KF   5         // filter size
#define PADF 2
#define NTAP 25

#define TILE 16        // output tile is TILE x TILE pixels
#define SW   (TILE + 2*PADF)   // 20: padded tile width/height
#define NPIX (TILE*TILE)       // 256 pixels per tile

// Shared memory layout (dynamic):
//   fs: SW*SW pixels * 8 float4 (swizzled)  = 20*20*8*16 = 51200 B
//   ts: NTAP * NPIX floats (tap-major)      = 25*256*4   = 25600 B
#define FS_BYTES (SW*SW*8*16)
#define SMEM_BYTES (FS_BYTES + NTAP*NPIX*4)

__global__ void __launch_bounds__(256, 2)
kpc2d_kernel(const float* __restrict__ feat,
             const float* __restrict__ kern,
             const float* __restrict__ bias,
             float* __restrict__ out)
{
    extern __shared__ char smem[];
    float4* fs = (float4*)smem;                    // [SW*SW][8] swizzled
    float*  ts = (float*)(smem + FS_BYTES);        // [NTAP][NPIX]

    const int tid = threadIdx.x;
    const int h0  = blockIdx.y * TILE;
    const int w0  = blockIdx.x * TILE;
    const int bz  = blockIdx.z;

    // ---------------- fill feat halo tile (zero-padded), swizzled ----------
    // swizzle: channel-group index xored with bit derived from column so that
    // pixels 4 apart land on different 64B halves of the 128B pixel block.
    #pragma unroll 1
    for (int idx = tid; idx < SW*SW*8; idx += 256) {
        const int cg = idx & 7;
        const int tp = idx >> 3;          // tile pixel 0..399
        const int tr = tp / SW;
        const int tc = tp - tr * SW;
        const int gh = h0 + tr - PADF;
        const int gw = w0 + tc - PADF;
        float4 v = make_float4(0.f, 0.f, 0.f, 0.f);
        if ((unsigned)gh < HH && (unsigned)gw < WW) {
            v = __ldg(((const float4*)(feat + ((size_t)((bz*HH + gh)*WW + gw) * CC))) + cg);
        }
        const int swz = ((tc >> 2) & 1) << 2;
        fs[tp * 8 + (cg ^ swz)] = v;
    }

    // ---------------- fill taps, transposed to [tap][pixel] ----------------
    #pragma unroll 1
    for (int idx = tid; idx < NTAP*NPIX; idx += 256) {
        const int pix = idx / NTAP;       // 0..255 (row-major in tile)
        const int tap = idx - pix * NTAP;
        const int pr  = pix >> 4;         // tile row
        const int pc  = pix & 15;         // tile col
        const float t = __ldg(kern + ((size_t)((bz*HH + h0 + pr)*WW + (w0 + pc)) * NTAP) + tap);
        ts[tap * NPIX + pix] = t;
    }

    __syncthreads();

    // ---------------- compute ---------------------------------------------
    // thread -> (cgslot 0..3, quad 0..63); quad -> (row 0..15, wq in {0,4,8,12})
    // each thread produces 4 consecutive w-pixels for channel groups
    // cgslot and cgslot+4 (two float4 accumulators per pixel).
    const int cgslot = tid & 3;
    const int qid    = tid >> 2;
    const int r      = qid >> 2;          // tile row
    const int wq     = (qid & 3) << 2;    // base col in tile

    const float4 bv0 = __ldg((const float4*)bias + cgslot);
    const float4 bv1 = __ldg((const float4*)bias + cgslot + 4);

    float4 acc0[4], acc1[4];
    #pragma unroll
    for (int p = 0; p < 4; p++) { acc0[p] = bv0; acc1[p] = bv1; }

    const int pixbase = r * TILE + wq;

    #pragma unroll
    for (int i = 0; i < KF; i++) {
        // sliding window: padded row r+i, padded cols wq .. wq+7
        const int rowb = (r + i) * SW;
        float4 fa0[8], fa1[8];
        #pragma unroll
        for (int x = 0; x < 8; x++) {
            const int col = wq + x;
            const int swz = ((col >> 2) & 1) << 2;
            const float4* pp = &fs[(rowb + col) * 8];
            fa0[x] = pp[cgslot | swz];
            fa1[x] = pp[cgslot | (swz ^ 4)];
        }
        #pragma unroll
        for (int j = 0; j < KF; j++) {
            const float* trow = &ts[(i * KF + j) * NPIX + pixbase];
            #pragma unroll
            for (int p = 0; p < 4; p++) {
                const float t = trow[p];
                const float4 f0 = fa0[j + p];
                const float4 f1 = fa1[j + p];
                acc0[p].x += f0.x * t; acc0[p].y += f0.y * t;
                acc0[p].z += f0.z * t; acc0[p].w += f0.w * t;
                acc1[p].x += f1.x * t; acc1[p].y += f1.y * t;
                acc1[p].z += f1.z * t; acc1[p].w += f1.w * t;
            }
        }
    }

    // ---------------- write out -------------------------------------------
    #pragma unroll
    for (int p = 0; p < 4; p++) {
        float4* op = (float4*)(out + ((size_t)((bz*HH + h0 + r)*WW + (w0 + wq + p)) * CC));
        op[cgslot]     = acc0[p];
        op[cgslot + 4] = acc1[p];
    }
}

extern "C" void kernel_launch(void* const* d_in, const int* in_sizes, int n_in,
                              void* d_out, int out_size)
{
    const float* feat = (const float*)d_in[0];
    const float* kern = (const float*)d_in[1];
    const float* bias = (const float*)d_in[2];
    float* out = (float*)d_out;

    static bool attr_set = false;
    if (!attr_set) {
        cudaFuncSetAttribute(kpc2d_kernel,
                             cudaFuncAttributeMaxDynamicSharedMemorySize,
                             SMEM_BYTES);
        attr_set = true;
    }

    dim3 grid(WW / TILE, HH / TILE, BB);   // 16 x 16 x 4 = 1024 blocks
    kpc2d_kernel<<<grid, 256, SMEM_BYTES>>>(feat, kern, bias, out);
}

// round 2
// speedup vs baseline: 1.2262x; 1.2262x over previous
#include <cuda_runtime.h>

// Problem constants
#define BB   4
#define HH   256
#define WW   256
#define CC   32        // channels == warp lanes
#define KF   5
#define NTAP 25

#define TW   16        // tile width  (pixels per warp-row)
#define TH   8         // tile height (one warp per row, 8 warps = 256 thr)
#define HW   (TW + 4)  // 20: halo width
#define HHT  (TH + 4)  // 12: halo height
#define TS_STRIDE 260  // transposed tap row stride (mult of 4 -> 16B aligned float4)

#define FS_FLOATS (HHT * HW * CC)          // 12*20*32 = 7680 floats (30720 B)
#define TS_FLOATS (NTAP * TS_STRIDE)       // 25*260   = 6500 floats (26000 B)
#define SMEM_BYTES ((FS_FLOATS + TS_FLOATS) * 4)

__global__ void __launch_bounds__(256, 3)
kpc2d_kernel(const float* __restrict__ feat,
             const float* __restrict__ kern,
             const float* __restrict__ bias,
             float* __restrict__ out)
{
    extern __shared__ float smem[];
    float* fs = smem;                 // [HHT*HW][32], bank == lane, conflict-free
    float* ts = smem + FS_FLOATS;     // [NTAP][TS_STRIDE], broadcast reads

    const int tid  = threadIdx.x;
    const int lane = tid & 31;        // channel
    const int wid  = tid >> 5;        // tile row 0..7
    const int w0   = blockIdx.x * TW;
    const int h0   = blockIdx.y * TH;
    const int bz   = blockIdx.z;

    const float bv = __ldg(bias + lane);

    // ---- feat halo fill: float4 coalesced gmem, conflict-free STS.128 ----
    const float4* featv = (const float4*)feat;
    float4* fsv = (float4*)fs;
    #pragma unroll 1
    for (int idx = tid; idx < HHT * HW * 8; idx += 256) {
        const int cg = idx & 7;
        const int tp = idx >> 3;
        const int tr = tp / HW;
        const int tc = tp - tr * HW;
        const int gh = h0 + tr - 2;
        const int gw = w0 + tc - 2;
        float4 v = make_float4(0.f, 0.f, 0.f, 0.f);
        if ((unsigned)gh < HH && (unsigned)gw < WW)
            v = __ldg(featv + ((size_t)((bz * HH + gh) * WW + gw)) * 8 + cg);
        fsv[tp * 8 + cg] = v;
    }

    // ---- tap fill: contiguous gmem reads per tile row, transposed store ----
    // kern for one tile row = 16 px * 25 taps = 400 contiguous floats.
    #pragma unroll 1
    for (int idx = tid; idx < TH * TW * NTAP; idx += 256) {
        const int tr = idx / (TW * NTAP);
        const int k  = idx - tr * (TW * NTAP);
        const float v = __ldg(kern + ((size_t)((bz * HH + h0 + tr) * WW + w0)) * NTAP + k);
        const int tc = k / NTAP;
        const int t  = k - tc * NTAP;
        ts[t * TS_STRIDE + tr * TW + tc] = v;
    }

    __syncthreads();

    // ---- compute: warp = one output row, lane = channel ----
    float acc[TW];
    #pragma unroll
    for (int p = 0; p < TW; p++) acc[p] = bv;

    const int prow = wid * TW;   // pixel base within tile (row-major)

    #pragma unroll
    for (int i = 0; i < KF; i++) {
        // load the 20-wide feat window for padded row (wid+i), this lane's channel
        float fr[HW];
        const float* frow = fs + ((wid + i) * HW) * CC + lane;
        #pragma unroll
        for (int c = 0; c < HW; c++) fr[c] = frow[c * CC];

        #pragma unroll
        for (int j = 0; j < KF; j++) {
            const float* trow = ts + (i * KF + j) * TS_STRIDE + prow;
            #pragma unroll
            for (int pg = 0; pg < 4; pg++) {
                const float4 t4 = *(const float4*)(trow + pg * 4);  // uniform broadcast
                acc[pg * 4 + 0] += fr[pg * 4 + 0 + j] * t4.x;
                acc[pg * 4 + 1] += fr[pg * 4 + 1 + j] * t4.y;
                acc[pg * 4 + 2] += fr[pg * 4 + 2 + j] * t4.z;
                acc[pg * 4 + 3] += fr[pg * 4 + 3 + j] * t4.w;
            }
        }
    }

    // ---- store: 16 coalesced 128B rows ----
    float* orow = out + ((size_t)((bz * HH + h0 + wid) * WW + w0)) * CC + lane;
    #pragma unroll
    for (int p = 0; p < TW; p++) orow[p * CC] = acc[p];
}

extern "C" void kernel_launch(void* const* d_in, const int* in_sizes, int n_in,
                              void* d_out, int out_size)
{
    const float* feat = (const float*)d_in[0];
    const float* kern = (const float*)d_in[1];
    const float* bias = (const float*)d_in[2];
    float* out = (float*)d_out;

    static bool attr_set = false;
    if (!attr_set) {
        cudaFuncSetAttribute(kpc2d_kernel,
                             cudaFuncAttributeMaxDynamicSharedMemorySize,
                             SMEM_BYTES);
        attr_set = true;
    }

    dim3 grid(WW / TW, HH / TH, BB);   // 16 x 32 x 4 = 2048 blocks
    kpc2d_kernel<<<grid, 256, SMEM_BYTES>>>(feat, kern, bias, out);
}

// round 3
// speedup vs baseline: 1.6997x; 1.3861x over previous
#include <cuda_runtime.h>

#define BB   4
#define HH   256
#define WW   256
#define CC   32        // channels == warp lanes
#define KF   5
#define NTAP 25

#define TW   16        // tile width (pixels per warp-row)
#define TH   8         // tile height (one warp per row)
#define TS_STRIDE 132  // [tap][pixel] row stride: 128 px + pad (mult of 4, !=0 mod 32)
#define SMEM_BYTES (NTAP * TS_STRIDE * 4)   // 13200 B

__global__ void __launch_bounds__(256, 4)
kpc2d_kernel(const float* __restrict__ feat,
             const float* __restrict__ kern,
             const float* __restrict__ bias,
             float* __restrict__ out)
{
    extern __shared__ float ts[];     // [NTAP][TS_STRIDE] transposed taps

    const int tid  = threadIdx.x;
    const int lane = tid & 31;        // channel
    const int wid  = tid >> 5;        // tile row 0..7
    const int w0   = blockIdx.x * TW;
    const int h0   = blockIdx.y * TH;
    const int bz   = blockIdx.z;

    // ---- tap fill: coalesced gmem, transposed STS (~3.5-way, small) ----
    // kern for one tile row = TW*NTAP = 400 contiguous floats.
    #pragma unroll 1
    for (int idx = tid; idx < TH * TW * NTAP; idx += 256) {
        const int tr = idx / (TW * NTAP);
        const int k  = idx - tr * (TW * NTAP);
        const float v = __ldg(kern + ((size_t)((bz * HH + h0 + tr) * WW + w0)) * NTAP + k);
        const int tc = k / NTAP;          // pixel col in tile
        const int t  = k - tc * NTAP;     // tap id
        ts[t * TS_STRIDE + tr * TW + tc] = v;
    }

    const float bv = __ldg(bias + lane);
    __syncthreads();

    // ---- compute: warp = one output row, lane = channel, feat via L1 ----
    float acc[TW];
    #pragma unroll
    for (int p = 0; p < TW; p++) acc[p] = bv;

    const int pixbase = wid * TW;
    const bool interior = (h0 >= 2) && (h0 + TH + 2 <= HH) &&
                          (w0 >= 2) && (w0 + TW + 2 <= WW);

    if (interior) {
        #pragma unroll
        for (int i = 0; i < KF; i++) {
            const int gh = h0 + wid + i - 2;
            const float* frow =
                feat + ((size_t)((bz * HH + gh) * WW + (w0 - 2))) * CC + lane;
            float fr[TW + 4];
            #pragma unroll
            for (int c = 0; c < TW + 4; c++) fr[c] = __ldg(frow + c * CC);

            #pragma unroll
            for (int j = 0; j < KF; j++) {
                const float* trow = ts + (i * KF + j) * TS_STRIDE + pixbase;
                #pragma unroll
                for (int pg = 0; pg < 4; pg++) {
                    const float4 t4 = *(const float4*)(trow + pg * 4);
                    acc[pg * 4 + 0] += fr[pg * 4 + 0 + j] * t4.x;
                    acc[pg * 4 + 1] += fr[pg * 4 + 1 + j] * t4.y;
                    acc[pg * 4 + 2] += fr[pg * 4 + 2 + j] * t4.z;
                    acc[pg * 4 + 3] += fr[pg * 4 + 3 + j] * t4.w;
                }
            }
        }
    } else {
        #pragma unroll
        for (int i = 0; i < KF; i++) {
            const int gh = h0 + wid + i - 2;
            const bool rok = (unsigned)gh < HH;
            const float* frow =
                feat + ((size_t)((bz * HH + gh) * WW + (w0 - 2))) * CC + lane;
            float fr[TW + 4];
            #pragma unroll
            for (int c = 0; c < TW + 4; c++) {
                const int gw = w0 + c - 2;
                fr[c] = (rok && (unsigned)gw < WW) ? __ldg(frow + c * CC) : 0.f;
            }

            #pragma unroll
            for (int j = 0; j < KF; j++) {
                const float* trow = ts + (i * KF + j) * TS_STRIDE + pixbase;
                #pragma unroll
                for (int pg = 0; pg < 4; pg++) {
                    const float4 t4 = *(const float4*)(trow + pg * 4);
                    acc[pg * 4 + 0] += fr[pg * 4 + 0 + j] * t4.x;
                    acc[pg * 4 + 1] += fr[pg * 4 + 1 + j] * t4.y;
                    acc[pg * 4 + 2] += fr[pg * 4 + 2 + j] * t4.z;
                    acc[pg * 4 + 3] += fr[pg * 4 + 3 + j] * t4.w;
                }
            }
        }
    }

    // ---- store: 16 coalesced 128B rows ----
    float* orow = out + ((size_t)((bz * HH + h0 + wid) * WW + w0)) * CC + lane;
    #pragma unroll
    for (int p = 0; p < TW; p++) orow[p * CC] = acc[p];
}

extern "C" void kernel_launch(void* const* d_in, const int* in_sizes, int n_in,
                              void* d_out, int out_size)
{
    const float* feat = (const float*)d_in[0];
    const float* kern = (const float*)d_in[1];
    const float* bias = (const float*)d_in[2];
    float* out = (float*)d_out;

    dim3 grid(WW / TW, HH / TH, BB);   // 16 x 32 x 4 = 2048 blocks
    kpc2d_kernel<<<grid, 256, SMEM_BYTES>>>(feat, kern, bias, out);
}

// round 4
// speedup vs baseline: 1.7558x; 1.0330x over previous
#include <cuda_runtime.h>

#define BB   4
#define HH   256
#define WW   256
#define CC   32
#define KF   5
#define NTAP 25

#define TW   16                 // tile width (pixels)
#define TH   8                  // tile height (one warp per row)
#define NPIX (TW*TH)            // 128 pixels per block
#define TS_STRIDE 130           // f32x2 units per tap row (pad: 130*2 % 32 = 4)
#define SMEM_BYTES (NTAP * TS_STRIDE * 8)   // 26000 B

typedef unsigned long long u64;

__device__ __forceinline__ void fma2(u64& d, u64 a, u64 b) {
    asm("fma.rn.f32x2 %0, %1, %2, %0;" : "+l"(d) : "l"(a), "l"(b));
}
__device__ __forceinline__ u64 splat2(float v) {
    unsigned int b = __float_as_uint(v);
    return ((u64)b << 32) | b;
}

__global__ void __launch_bounds__(256, 4)
kpc2d_kernel(const float* __restrict__ feat,
             const float* __restrict__ kern,
             const float* __restrict__ bias,
             float* __restrict__ out)
{
    extern __shared__ u64 ts[];   // [NTAP][TS_STRIDE] splatted taps (t,t)

    const int tid  = threadIdx.x;
    const int lane = tid & 31;
    const int wid  = tid >> 5;          // tile row 0..7
    const int cp   = lane & 15;         // channel pair 0..15
    const int half = lane >> 4;         // pixel half 0/1
    const int w0   = blockIdx.x * TW;
    const int h0   = blockIdx.y * TH;
    const int bz   = blockIdx.z;

    // ---- tap fill: coalesced gmem reads, splatted transposed stores ----
    // kern slice per tile row = TW*NTAP = 400 contiguous floats.
    #pragma unroll 1
    for (int idx = tid; idx < TH * TW * NTAP; idx += 256) {
        const int row = idx / (TW * NTAP);
        const int k   = idx - row * (TW * NTAP);
        const float v = __ldg(kern + ((size_t)((bz * HH + h0 + row) * WW + w0)) * NTAP + k);
        const int col = k / NTAP;
        const int tap = k - col * NTAP;
        ts[tap * TS_STRIDE + row * TW + col] = splat2(v);
    }

    const u64 bv = *(const u64*)(bias + 2 * cp);
    __syncthreads();

    // ---- compute: warp = one output row; thread = 8 pixels x 2 channels ----
    u64 acc[8];
    #pragma unroll
    for (int p = 0; p < 8; p++) acc[p] = bv;

    const int pbase = half * 8;                  // pixel base within row
    const int tsbase = wid * TW + pbase;         // tap pixel base
    const bool interior = (h0 >= 2) && (h0 + TH + 2 <= HH) &&
                          (w0 >= 2) && (w0 + TW + 2 <= WW);

    if (interior) {
        #pragma unroll
        for (int i = 0; i < KF; i++) {
            const int gh = h0 + wid + i - 2;
            const char* frow = (const char*)
                (feat + ((size_t)((bz * HH + gh) * WW + (w0 + pbase - 2))) * CC + 2 * cp);
            u64 wr[12];
            #pragma unroll
            for (int c = 0; c < 12; c++)
                wr[c] = __ldg((const u64*)(frow + c * (CC * 4)));

            #pragma unroll
            for (int j = 0; j < KF; j++) {
                const u64* tp = ts + (i * KF + j) * TS_STRIDE + tsbase;
                const ulonglong2 t01 = *(const ulonglong2*)(tp + 0);
                const ulonglong2 t23 = *(const ulonglong2*)(tp + 2);
                const ulonglong2 t45 = *(const ulonglong2*)(tp + 4);
                const ulonglong2 t67 = *(const ulonglong2*)(tp + 6);
                fma2(acc[0], wr[0 + j], t01.x);
                fma2(acc[1], wr[1 + j], t01.y);
                fma2(acc[2], wr[2 + j], t23.x);
                fma2(acc[3], wr[3 + j], t23.y);
                fma2(acc[4], wr[4 + j], t45.x);
                fma2(acc[5], wr[5 + j], t45.y);
                fma2(acc[6], wr[6 + j], t67.x);
                fma2(acc[7], wr[7 + j], t67.y);
            }
        }
    } else {
        #pragma unroll
        for (int i = 0; i < KF; i++) {
            const int gh = h0 + wid + i - 2;
            const bool rok = (unsigned)gh < HH;
            const char* frow = (const char*)
                (feat + ((size_t)((bz * HH + gh) * WW + (w0 + pbase - 2))) * CC + 2 * cp);
            u64 wr[12];
            #pragma unroll
            for (int c = 0; c < 12; c++) {
                const int gw = w0 + pbase + c - 2;
                wr[c] = (rok && (unsigned)gw < WW)
                        ? __ldg((const u64*)(frow + c * (CC * 4))) : 0ULL;
            }

            #pragma unroll
            for (int j = 0; j < KF; j++) {
                const u64* tp = ts + (i * KF + j) * TS_STRIDE + tsbase;
                const ulonglong2 t01 = *(const ulonglong2*)(tp + 0);
                const ulonglong2 t23 = *(const ulonglong2*)(tp + 2);
                const ulonglong2 t45 = *(const ulonglong2*)(tp + 4);
                const ulonglong2 t67 = *(const ulonglong2*)(tp + 6);
                fma2(acc[0], wr[0 + j], t01.x);
                fma2(acc[1], wr[1 + j], t01.y);
                fma2(acc[2], wr[2 + j], t23.x);
                fma2(acc[3], wr[3 + j], t23.y);
                fma2(acc[4], wr[4 + j], t45.x);
                fma2(acc[5], wr[5 + j], t45.y);
                fma2(acc[6], wr[6 + j], t67.x);
                fma2(acc[7], wr[7 + j], t67.y);
            }
        }
    }

    // ---- store: STG.64 per pixel, coalesced 256B per instruction ----
    char* orow = (char*)
        (out + ((size_t)((bz * HH + h0 + wid) * WW + (w0 + pbase))) * CC + 2 * cp);
    #pragma unroll
    for (int p = 0; p < 8; p++)
        *(u64*)(orow + p * (CC * 4)) = acc[p];
}

extern "C" void kernel_launch(void* const* d_in, const int* in_sizes, int n_in,
                              void* d_out, int out_size)
{
    const float* feat = (const float*)d_in[0];
    const float* kern = (const float*)d_in[1];
    const float* bias = (const float*)d_in[2];
    float* out = (float*)d_out;

    static bool attr_set = false;
    if (!attr_set) {
        cudaFuncSetAttribute(kpc2d_kernel,
                             cudaFuncAttributeMaxDynamicSharedMemorySize,
                             SMEM_BYTES);
        attr_set = true;
    }

    dim3 grid(WW / TW, HH / TH, BB);   // 16 x 32 x 4 = 2048 blocks
    kpc2d_kernel<<<grid, 256, SMEM_BYTES>>>(feat, kern, bias, out);
}

// round 5
// speedup vs baseline: 1.9755x; 1.1251x over previous
#include <cuda_runtime.h>

#define BB   4
#define HH   256
#define WW   256
#define CC   32
#define KF   5
#define NTAP 25

#define TW   16                 // tile width (pixels)
#define TH   16                 // tile height (2 rows per warp, 8 warps)
#define TSS  258                // u64 stride per tap row (16B aligned, padded)
#define SMEM_BYTES (NTAP * TSS * 8)   // 51600 B

typedef unsigned long long u64;

__device__ __forceinline__ void fma2(u64& d, u64 a, u64 b) {
    asm("fma.rn.f32x2 %0, %1, %2, %0;" : "+l"(d) : "l"(a), "l"(b));
}
__device__ __forceinline__ u64 splat2(float v) {
    unsigned int b = __float_as_uint(v);
    return ((u64)b << 32) | b;
}

// accumulate one (feat-row, out-row) pair: 5 j-taps, 8 pixels, 2 channels
__device__ __forceinline__ void accum(u64* __restrict__ acc,
                                      const u64* __restrict__ wr,
                                      const u64* __restrict__ ts,
                                      int irow, int pix)
{
    #pragma unroll
    for (int j = 0; j < KF; j++) {
        const u64* tp = ts + (irow * KF + j) * TSS + pix;
        const ulonglong2 t01 = *(const ulonglong2*)(tp + 0);
        const ulonglong2 t23 = *(const ulonglong2*)(tp + 2);
        const ulonglong2 t45 = *(const ulonglong2*)(tp + 4);
        const ulonglong2 t67 = *(const ulonglong2*)(tp + 6);
        fma2(acc[0], wr[0 + j], t01.x);
        fma2(acc[1], wr[1 + j], t01.y);
        fma2(acc[2], wr[2 + j], t23.x);
        fma2(acc[3], wr[3 + j], t23.y);
        fma2(acc[4], wr[4 + j], t45.x);
        fma2(acc[5], wr[5 + j], t45.y);
        fma2(acc[6], wr[6 + j], t67.x);
        fma2(acc[7], wr[7 + j], t67.y);
    }
}

__global__ void __launch_bounds__(256, 3)
kpc2d_kernel(const float* __restrict__ feat,
             const float* __restrict__ kern,
             const float* __restrict__ bias,
             float* __restrict__ out)
{
    extern __shared__ u64 ts[];   // [NTAP][TSS] splatted taps (t,t)

    const int tid  = threadIdx.x;
    const int lane = tid & 31;
    const int wid  = tid >> 5;          // warp -> 2 tile rows
    const int cp   = lane & 15;         // channel pair
    const int half = lane >> 4;         // pixel half (0/1)
    const int w0   = blockIdx.x * TW;
    const int h0   = blockIdx.y * TH;
    const int bz   = blockIdx.z;

    // ---- tap fill: LDG.128, magic-divide indexing, splatted STS.64 ----
    // per tile row: TW*NTAP = 400 floats = 100 float4; 16 rows = 1600 float4
    const float4* kern4 = (const float4*)kern;
    #pragma unroll 1
    for (unsigned idx4 = tid; idx4 < TH * TW * NTAP / 4; idx4 += 256) {
        const unsigned row = idx4 / 100u;              // small-range div
        const unsigned k4  = (idx4 - row * 100u) * 4u; // 0..396
        const size_t fidx = ((size_t)((bz * HH + h0 + (int)row) * WW + w0)) * NTAP + k4;
        const float4 v = __ldg(kern4 + (fidx >> 2));
        unsigned col = (k4 * 1311u) >> 15;             // k4/25 for k4<400
        unsigned tap = k4 - col * 25u;
        const unsigned pb = row * TW;
        float vv[4] = {v.x, v.y, v.z, v.w};
        #pragma unroll
        for (int e = 0; e < 4; e++) {
            ts[tap * TSS + pb + col] = splat2(vv[e]);
            if (++tap == 25u) { tap = 0u; col++; }
        }
    }

    const u64 bv = *(const u64*)(bias + 2 * cp);
    __syncthreads();

    // ---- compute: warp = 2 output rows; thread = 8 px x 2 ch x 2 rows ----
    u64 a0[8], a1[8];
    #pragma unroll
    for (int p = 0; p < 8; p++) { a0[p] = bv; a1[p] = bv; }

    const int r0    = wid * 2;
    const int pbase = half * 8;
    const int pix0  = r0 * TW + pbase;
    const int pix1  = pix0 + TW;
    const bool interior = (h0 >= 2) && (h0 + TH + 2 <= HH) &&
                          (w0 >= 2) && (w0 + TW + 2 <= WW);

    if (interior) {
        #pragma unroll
        for (int fr = 0; fr < 6; fr++) {
            const int gh = h0 + r0 + fr - 2;
            const char* frow = (const char*)
                (feat + ((size_t)((bz * HH + gh) * WW + (w0 + pbase - 2))) * CC + 2 * cp);
            u64 wr[12];
            #pragma unroll
            for (int c = 0; c < 12; c++)
                wr[c] = __ldg((const u64*)(frow + c * (CC * 4)));
            if (fr < 5) accum(a0, wr, ts, fr,     pix0);
            if (fr > 0) accum(a1, wr, ts, fr - 1, pix1);
        }
    } else {
        #pragma unroll 1
        for (int fr = 0; fr < 6; fr++) {
            const int gh = h0 + r0 + fr - 2;
            const bool rok = (unsigned)gh < HH;
            const char* frow = (const char*)
                (feat + ((size_t)((bz * HH + gh) * WW + (w0 + pbase - 2))) * CC + 2 * cp);
            u64 wr[12];
            #pragma unroll
            for (int c = 0; c < 12; c++) {
                const int gw = w0 + pbase + c - 2;
                wr[c] = (rok && (unsigned)gw < WW)
                        ? __ldg((const u64*)(frow + c * (CC * 4))) : 0ULL;
            }
            if (fr < 5) accum(a0, wr, ts, fr,     pix0);
            if (fr > 0) accum(a1, wr, ts, fr - 1, pix1);
        }
    }

    // ---- store: 2 rows x 8 px, STG.64, 256B coalesced per warp-instr ----
    char* o0 = (char*)
        (out + ((size_t)((bz * HH + h0 + r0) * WW + (w0 + pbase))) * CC + 2 * cp);
    char* o1 = o0 + (size_t)WW * CC * 4;
    #pragma unroll
    for (int p = 0; p < 8; p++) {
        *(u64*)(o0 + p * (CC * 4)) = a0[p];
        *(u64*)(o1 + p * (CC * 4)) = a1[p];
    }
}

extern "C" void kernel_launch(void* const* d_in, const int* in_sizes, int n_in,
                              void* d_out, int out_size)
{
    const float* feat = (const float*)d_in[0];
    const float* kern = (const float*)d_in[1];
    const float* bias = (const float*)d_in[2];
    float* out = (float*)d_out;

    static bool attr_set = false;
    if (!attr_set) {
        cudaFuncSetAttribute(kpc2d_kernel,
                             cudaFuncAttributeMaxDynamicSharedMemorySize,
                             SMEM_BYTES);
        attr_set = true;
    }

    dim3 grid(WW / TW, HH / TH, BB);   // 16 x 16 x 4 = 1024 blocks
    kpc2d_kernel<<<grid, 256, SMEM_BYTES>>>(feat, kern, bias, out);
}